// round 1
// baseline (speedup 1.0000x reference)
#include <cuda_runtime.h>
#include <math.h>

// ============================================================================
// Flash-attention (padding-mask) fp32 SIMT baseline for GB300.
//  - grid: (SEQ/64, BS); block: 256 threads; 1 block/SM (117KB smem)
//  - Stage A: S = scale * Q K^T  (4q x 4k register tile per thread)
//  - online softmax (half-warp shfl reductions across the 16 "tx" lanes)
//  - Stage C: O += P V  via smem-staged P (4q x 8d register tile per thread)
//  - keys >= valid_len skipped: exp(-1e6 - m) == 0.0f exactly in fp32,
//    so truncating the k-loop at ceil(valid/64) is bit-identical.
// ============================================================================

namespace {

constexpr int kD  = 128;
constexpr int BQ  = 64;
constexpr int BK  = 64;
constexpr int NT  = 256;
constexpr int QP  = kD + 1;   // 129: pitch for Qs/Ks (scalar access, low conflict)
constexpr int VP  = kD + 4;   // 132: pitch for Vs (float4-aligned rows)
constexpr int PP  = BQ + 4;   // 68 : pitch for Ps (float4-aligned rows)
constexpr float kScale = 0.08838834764831845f;  // 1/sqrt(128)

__global__ __launch_bounds__(NT, 1)
void attn_kernel(const float* __restrict__ Q, const float* __restrict__ K,
                 const float* __restrict__ V, const int* __restrict__ vlen,
                 float* __restrict__ O, int seq)
{
    extern __shared__ float sm[];
    float* Qs = sm;                       // BQ * QP
    float* Ks = Qs + BQ * QP;             // BK * QP
    float* Vs = Ks + BK * QP;             // BK * VP
    float* Ps = Vs + BK * VP;             // BK * PP   (P stored [k][q])

    const int b   = blockIdx.y;
    const int q0  = blockIdx.x * BQ;
    const int tid = threadIdx.x;
    const int tx  = tid & 15;             // k-group (stage A) / d-group (stage C)
    const int ty  = tid >> 4;             // q-group (0..15)

    const float* Qg = Q + ((size_t)b * seq + q0) * kD;
    const float* Kg = K + (size_t)b * seq * kD;
    const float* Vg = V + (size_t)b * seq * kD;
    const int valid  = vlen[b];
    const int ntiles = (valid + BK - 1) / BK;

    // ---- load Q tile (natural [q][d], pitch QP) ----
    for (int i = tid; i < BQ * (kD / 4); i += NT) {
        int r  = i >> 5;
        int d4 = (i & 31) << 2;
        float4 v = *(const float4*)(Qg + (size_t)r * kD + d4);
        float* dst = Qs + r * QP + d4;
        dst[0] = v.x; dst[1] = v.y; dst[2] = v.z; dst[3] = v.w;
    }

    float m[4], l[4], o[4][8];
    #pragma unroll
    for (int i = 0; i < 4; ++i) {
        m[i] = -INFINITY; l[i] = 0.f;
        #pragma unroll
        for (int j = 0; j < 8; ++j) o[i][j] = 0.f;
    }

    for (int t = 0; t < ntiles; ++t) {
        __syncthreads();   // protect smem reuse vs previous tile's stage C
        const int k0 = t * BK;

        // ---- load K (pitch QP, scalar stores) + V (pitch VP, float4) ----
        for (int i = tid; i < BK * (kD / 4); i += NT) {
            int r  = i >> 5;
            int d4 = (i & 31) << 2;
            const float* kp = Kg + (size_t)(k0 + r) * kD + d4;
            float4 kv = *(const float4*)kp;
            float* kd = Ks + r * QP + d4;
            kd[0] = kv.x; kd[1] = kv.y; kd[2] = kv.z; kd[3] = kv.w;
            const float* vp = Vg + (size_t)(k0 + r) * kD + d4;
            *(float4*)(Vs + r * VP + d4) = *(const float4*)vp;
        }
        __syncthreads();

        // ---- Stage A: S = Q K^T (raw dot; scale applied in softmax) ----
        float s[4][4];
        #pragma unroll
        for (int i = 0; i < 4; ++i)
            #pragma unroll
            for (int j = 0; j < 4; ++j) s[i][j] = 0.f;

        const float* qrow = Qs + (ty * 4) * QP;
        const float* krow = Ks + (tx * 4) * QP;
        #pragma unroll 8
        for (int d = 0; d < kD; ++d) {
            float qf[4], kf[4];
            #pragma unroll
            for (int i = 0; i < 4; ++i) qf[i] = qrow[i * QP + d];
            #pragma unroll
            for (int j = 0; j < 4; ++j) kf[j] = krow[j * QP + d];
            #pragma unroll
            for (int i = 0; i < 4; ++i)
                #pragma unroll
                for (int j = 0; j < 4; ++j)
                    s[i][j] = fmaf(qf[i], kf[j], s[i][j]);
        }

        // ---- mask + scale + per-row tile max ----
        const int kbase = k0 + tx * 4;
        float tmax[4];
        #pragma unroll
        for (int i = 0; i < 4; ++i) {
            tmax[i] = -INFINITY;
            #pragma unroll
            for (int j = 0; j < 4; ++j) {
                float v = (kbase + j < valid) ? s[i][j] * kScale : -INFINITY;
                s[i][j] = v;
                tmax[i] = fmaxf(tmax[i], v);
            }
        }
        #pragma unroll
        for (int off = 8; off; off >>= 1)
            #pragma unroll
            for (int i = 0; i < 4; ++i)
                tmax[i] = fmaxf(tmax[i], __shfl_xor_sync(0xffffffffu, tmax[i], off));

        // ---- online softmax update ----
        float alpha[4], tsum[4];
        #pragma unroll
        for (int i = 0; i < 4; ++i) {
            float mn = fmaxf(m[i], tmax[i]);   // finite: tile has >=1 valid key
            alpha[i] = __expf(m[i] - mn);      // first tile: exp(-inf)=0
            m[i] = mn;
            float su = 0.f;
            #pragma unroll
            for (int j = 0; j < 4; ++j) {
                float p = __expf(s[i][j] - mn);  // masked: exp(-inf)=0
                s[i][j] = p;
                su += p;
            }
            tsum[i] = su;
        }
        #pragma unroll
        for (int off = 8; off; off >>= 1)
            #pragma unroll
            for (int i = 0; i < 4; ++i)
                tsum[i] += __shfl_xor_sync(0xffffffffu, tsum[i], off);
        #pragma unroll
        for (int i = 0; i < 4; ++i) {
            l[i] = l[i] * alpha[i] + tsum[i];
            #pragma unroll
            for (int j = 0; j < 8; ++j) o[i][j] *= alpha[i];
        }

        // ---- stage P through smem: Ps[k][q] ----
        #pragma unroll
        for (int j = 0; j < 4; ++j)
            *(float4*)(Ps + (tx * 4 + j) * PP + ty * 4) =
                make_float4(s[0][j], s[1][j], s[2][j], s[3][j]);
        __syncthreads();

        // ---- Stage C: O[q][d] += P[k][q] * V[k][d] ----
        // thread owns q = ty*4..+3, d = {tx*4..+3, 64+tx*4..+3}
        #pragma unroll 4
        for (int k = 0; k < BK; ++k) {
            float4 p  = *(const float4*)(Ps + k * PP + ty * 4);
            float4 v0 = *(const float4*)(Vs + k * VP + tx * 4);
            float4 v1 = *(const float4*)(Vs + k * VP + 64 + tx * 4);
            float pf[4] = {p.x, p.y, p.z, p.w};
            float vf[8] = {v0.x, v0.y, v0.z, v0.w, v1.x, v1.y, v1.z, v1.w};
            #pragma unroll
            for (int i = 0; i < 4; ++i)
                #pragma unroll
                for (int j = 0; j < 8; ++j)
                    o[i][j] = fmaf(pf[i], vf[j], o[i][j]);
        }
    }

    // ---- epilogue: O /= l, write coalesced ----
    float* Og = O + ((size_t)b * seq + q0) * kD;
    #pragma unroll
    for (int i = 0; i < 4; ++i) {
        float inv = 1.0f / l[i];
        float4 r0 = make_float4(o[i][0] * inv, o[i][1] * inv,
                                o[i][2] * inv, o[i][3] * inv);
        float4 r1 = make_float4(o[i][4] * inv, o[i][5] * inv,
                                o[i][6] * inv, o[i][7] * inv);
        *(float4*)(Og + (size_t)(ty * 4 + i) * kD + tx * 4)      = r0;
        *(float4*)(Og + (size_t)(ty * 4 + i) * kD + 64 + tx * 4) = r1;
    }
}

}  // namespace

extern "C" void kernel_launch(void* const* d_in, const int* in_sizes, int n_in,
                              void* d_out, int out_size)
{
    const float* Q    = (const float*)d_in[0];
    const float* K    = (const float*)d_in[1];
    const float* V    = (const float*)d_in[2];
    const int*   vlen = (const int*)d_in[3];
    float*       O    = (float*)d_out;

    const int bs  = in_sizes[3];                         // 8
    const int seq = in_sizes[0] / (bs * kD);             // 2048

    const int smemBytes = (BQ * QP + BK * QP + BK * VP + BK * PP) * (int)sizeof(float);
    cudaFuncSetAttribute(attn_kernel, cudaFuncAttributeMaxDynamicSharedMemorySize,
                         smemBytes);

    dim3 grid(seq / BQ, bs);
    attn_kernel<<<grid, NT, smemBytes>>>(Q, K, V, vlen, O, seq);
}